// round 10
// baseline (speedup 1.0000x reference)
#include <cuda_runtime.h>
#include <cstdint>

// DiverseSiblingsSearch on GB300 — fused 2-pass (DRAM stream + L2 re-read) threshold-select.
// lprobs: (128, 5, 50257) f32, scores: (128, 5, 10) f32, step: int scalar (=10).
// Output (f32): final_scores (128,10) | final_indices (128,10) | final_beams (128,10).

#define BSZ     128
#define BEAM    5
#define VOCAB   50257
#define KSEL    10
#define ROWS    (BSZ * BEAM)
#define T       256
#define NWARP   (T / 32)
#define CAP     1024
#define DIV_RATE 0.5f
#define NEG_INF __int_as_float(0xff800000u)
#define IDX_INF 0x7fffffff

// Inter-block scratch (no allocations allowed).
__device__ float g_cand_val[ROWS * KSEL];
__device__ int   g_cand_idx[ROWS * KSEL];
__device__ int   g_batch_done[BSZ];            // zero-init; reset by finisher each replay

__device__ __forceinline__ bool better(float v1, int i1, float v2, int i2) {
    // JAX top_k stability: larger value wins; ties -> smaller index wins.
    return (v1 > v2) || (v1 == v2 && i1 < i2);
}

__device__ __forceinline__ float4 max4(float4 a, float4 b) {
    return make_float4(fmaxf(a.x, b.x), fmaxf(a.y, b.y), fmaxf(a.z, b.z), fmaxf(a.w, b.w));
}

__global__ __launch_bounds__(T, 4)
void dss_kernel(const float* __restrict__ lprobs,
                const float* __restrict__ scores,
                const int* __restrict__ step_ptr,
                int score_last_dim,
                float* __restrict__ out) {
    __shared__ float    swtop[2 * NWARP];       // per-warp top-2 maxima
    __shared__ float    sthr;
    __shared__ unsigned scount;
    __shared__ float    cval[CAP];
    __shared__ int      cidx[CAP];

    const int row   = blockIdx.x;                 // row = batch * BEAM + beam
    const int batch = row / BEAM;
    const int tid   = threadIdx.x;
    const int lane  = tid & 31;
    const int wid   = tid >> 5;
    const float* __restrict__ rp = lprobs + (size_t)row * VOCAB;

    if (tid == 0) scount = 0u;

    // Alignment peel: row*VOCAB mod 4 == row mod 4.
    const int P     = (4 - (row & 3)) & 3;        // head elements (scalar)
    const int nv    = (VOCAB - P) >> 2;           // aligned float4 count
    const int tailn = (VOCAB - P) & 3;            // tail elements (scalar)
    const float4* __restrict__ rp4 = reinterpret_cast<const float4*>(rp + P);

    // ---- Pass 1: pure streaming max. 8 front-batched LDG.128 per thread
    // (MLP=8, no dependent stores) into 4 accumulators. ----
    float4 M0 = make_float4(NEG_INF, NEG_INF, NEG_INF, NEG_INF);
    float4 M1 = M0, M2 = M0, M3 = M0;
    int v = tid;
    for (; v + 7 * T < nv; v += 8 * T) {
        float4 a = rp4[v];         float4 b = rp4[v + T];
        float4 c = rp4[v + 2 * T]; float4 d = rp4[v + 3 * T];
        float4 e = rp4[v + 4 * T]; float4 f = rp4[v + 5 * T];
        float4 g = rp4[v + 6 * T]; float4 h = rp4[v + 7 * T];
        M0 = max4(M0, max4(a, e));
        M1 = max4(M1, max4(b, f));
        M2 = max4(M2, max4(c, g));
        M3 = max4(M3, max4(d, h));
    }
    for (; v < nv; v += T) M0 = max4(M0, rp4[v]);
    M0 = max4(max4(M0, M1), max4(M2, M3));
    float m = fmaxf(fmaxf(M0.x, M0.y), fmaxf(M0.z, M0.w));

    // ---- Per-warp top-2 (2 distinct elements per warp -> 2*NWARP subset) ----
    {
        float w1 = m;
        for (int off = 16; off; off >>= 1) w1 = fmaxf(w1, __shfl_xor_sync(0xffffffffu, w1, off));
        unsigned holders = __ballot_sync(0xffffffffu, m == w1);
        int first = __ffs(holders) - 1;
        float m2 = (lane == first) ? NEG_INF : m;
        float w2 = m2;
        for (int off = 16; off; off >>= 1) w2 = fmaxf(w2, __shfl_xor_sync(0xffffffffu, w2, off));
        if (lane == 0) { swtop[wid] = w1; swtop[NWARP + wid] = w2; }
    }
    __syncthreads();

    // ---- Threshold: 10th largest of the 2*NWARP sampled distinct elements.
    // k-th largest of a subset <= k-th largest of the row -> conservative. ----
    if (tid < 32) {
        float x = (lane < 2 * NWARP) ? swtop[lane] : NEG_INF;
        float t = NEG_INF;
        for (int r = 0; r < KSEL; ++r) {
            float bv = x;
            for (int off = 16; off; off >>= 1) bv = fmaxf(bv, __shfl_xor_sync(0xffffffffu, bv, off));
            unsigned holders = __ballot_sync(0xffffffffu, x == bv);
            int first = __ffs(holders) - 1;
            if (lane == first) x = NEG_INF;       // retire one instance
            t = bv;
        }
        if (lane == 0) sthr = t;
    }
    __syncthreads();
    const float thr = sthr;

    // ---- Pass 2: exact re-read (mostly L2-resident) and compress survivors ----
    for (v = tid; v < nv; v += T) {
        float4 a = rp4[v];
        int i0 = P + 4 * v;
        if (a.x >= thr) { unsigned p = atomicAdd(&scount, 1u); if (p < CAP) { cval[p] = a.x; cidx[p] = i0; } }
        if (a.y >= thr) { unsigned p = atomicAdd(&scount, 1u); if (p < CAP) { cval[p] = a.y; cidx[p] = i0 + 1; } }
        if (a.z >= thr) { unsigned p = atomicAdd(&scount, 1u); if (p < CAP) { cval[p] = a.z; cidx[p] = i0 + 2; } }
        if (a.w >= thr) { unsigned p = atomicAdd(&scount, 1u); if (p < CAP) { cval[p] = a.w; cidx[p] = i0 + 3; } }
    }
    if (tid == 0) {          // head elements, exact test
        for (int i = 0; i < P; ++i) {
            float x = rp[i];
            if (x >= thr) { unsigned p = atomicAdd(&scount, 1u); if (p < CAP) { cval[p] = x; cidx[p] = i; } }
        }
    }
    if (tid == 1) {          // tail elements, exact test
        for (int q = 0; q < tailn; ++q) {
            int i = P + 4 * nv + q;
            float x = rp[i];
            if (x >= thr) { unsigned p = atomicAdd(&scount, 1u); if (p < CAP) { cval[p] = x; cidx[p] = i; } }
        }
    }
    __syncthreads();

    const unsigned cnt   = scount;
    const int      stepv = step_ptr ? *step_ptr : KSEL;
    const float    base  = scores[row * score_last_dim + (stepv - 1)];

    if (cnt > CAP) {
        // Pathological mass-tie fallback: exact serial top-10 (never on random data).
        if (tid == 0) {
            float val[KSEL]; int idq[KSEL];
#pragma unroll
            for (int q = 0; q < KSEL; ++q) { val[q] = NEG_INF; idq[q] = IDX_INF; }
            for (int i = 0; i < VOCAB; ++i) {
                float x = rp[i];
                if (better(x, i, val[KSEL - 1], idq[KSEL - 1])) {
                    val[KSEL - 1] = x; idq[KSEL - 1] = i;
#pragma unroll
                    for (int q = KSEL - 1; q > 0; --q) {
                        if (better(val[q], idq[q], val[q - 1], idq[q - 1])) {
                            float tv = val[q]; val[q] = val[q - 1]; val[q - 1] = tv;
                            int   ti = idq[q]; idq[q] = idq[q - 1]; idq[q - 1] = ti;
                        }
                    }
                }
            }
#pragma unroll
            for (int r = 0; r < KSEL; ++r) {
                g_cand_val[row * KSEL + r] = (val[r] + base) - (float)(r + 1) * DIV_RATE;
                g_cand_idx[row * KSEL + r] = idq[r];
            }
        }
    } else {
        // Warp-parallel stable top-10 over the candidate set (values already exact).
        if (tid < 32) {
            for (int r = 0; r < KSEL; ++r) {
                float bv = NEG_INF; int bi = IDX_INF; int bp = -1;
                for (unsigned c = lane; c < cnt; c += 32) {
                    float x = cval[c]; int ix = cidx[c];
                    if (better(x, ix, bv, bi)) { bv = x; bi = ix; bp = (int)c; }
                }
                for (int off = 16; off; off >>= 1) {
                    float ov = __shfl_down_sync(0xffffffffu, bv, off);
                    int   oi = __shfl_down_sync(0xffffffffu, bi, off);
                    int   op = __shfl_down_sync(0xffffffffu, bp, off);
                    if (better(ov, oi, bv, bi)) { bv = ov; bi = oi; bp = op; }
                }
                if (lane == 0) {
                    // ((lprob + base) - penalty): reference op order -> bit-exact.
                    g_cand_val[row * KSEL + r] = (bv + base) - (float)(r + 1) * DIV_RATE;
                    g_cand_idx[row * KSEL + r] = bi;
                    cval[bp] = NEG_INF; cidx[bp] = IDX_INF;
                }
                __syncwarp();
            }
        }
    }

    // ---- Fused finisher: last beam-block of the batch does the 50->10 select ----
    int done = 0;
    if (tid == 0) {
        __threadfence();                               // release g_cand writes
        done = atomicAdd(&g_batch_done[batch], 1);
    }
    if (tid < 32) {
        done = __shfl_sync(0xffffffffu, done, 0);
        if (done == BEAM - 1) {
            __threadfence();                           // acquire peers' g_cand
            const int b50 = batch * BEAM * KSEL;
            float v0 = NEG_INF, v1 = NEG_INF;
            int   p0 = IDX_INF, p1 = IDX_INF;
            if (lane < BEAM * KSEL)      { v0 = __ldcg(&g_cand_val[b50 + lane]);      p0 = lane; }
            if (lane + 32 < BEAM * KSEL) { v1 = __ldcg(&g_cand_val[b50 + lane + 32]); p1 = lane + 32; }
            for (int r = 0; r < KSEL; ++r) {
                float bv; int bp;
                if (better(v0, p0, v1, p1)) { bv = v0; bp = p0; } else { bv = v1; bp = p1; }
                for (int off = 16; off; off >>= 1) {
                    float ov = __shfl_down_sync(0xffffffffu, bv, off);
                    int   op = __shfl_down_sync(0xffffffffu, bp, off);
                    if (better(ov, op, bv, bp)) { bv = ov; bp = op; }
                }
                bv = __shfl_sync(0xffffffffu, bv, 0);
                bp = __shfl_sync(0xffffffffu, bp, 0);
                if (lane == 0) {
                    out[batch * KSEL + r]                  = bv;                                   // scores
                    out[BSZ * KSEL + batch * KSEL + r]     = (float)__ldcg(&g_cand_idx[b50 + bp]); // indices
                    out[2 * BSZ * KSEL + batch * KSEL + r] = (float)(bp / KSEL);                   // beams
                }
                if (p0 == bp) { v0 = NEG_INF; p0 = IDX_INF; }
                if (p1 == bp) { v1 = NEG_INF; p1 = IDX_INF; }
            }
            if (lane == 0) atomicExch(&g_batch_done[batch], 0);   // reset for next replay
        }
    }
}

extern "C" void kernel_launch(void* const* d_in, const int* in_sizes, int n_in,
                              void* d_out, int out_size) {
    const float* lprobs = (const float*)d_in[0];
    const float* scores = (const float*)d_in[1];
    const int*   step   = (n_in >= 3) ? (const int*)d_in[2] : nullptr;
    const int score_last_dim = in_sizes[1] / ROWS;   // = 10

    dss_kernel<<<ROWS, T>>>(lprobs, scores, step, score_last_dim, (float*)d_out);
}

// round 11
// speedup vs baseline: 1.4807x; 1.4807x over previous
#include <cuda_runtime.h>
#include <cstdint>

// DiverseSiblingsSearch on GB300 — true single-pass: per-thread register top-3
// + sampled conservative threshold + exact suspicion check (no second pass).
// lprobs: (128, 5, 50257) f32, scores: (128, 5, 10) f32, step: int scalar (=10).
// Output (f32): final_scores (128,10) | final_indices (128,10) | final_beams (128,10).

#define BSZ     128
#define BEAM    5
#define VOCAB   50257
#define KSEL    10
#define ROWS    (BSZ * BEAM)
#define T       256
#define NWARP   (T / 32)
#define CAP     1024
#define DIV_RATE 0.5f
#define NEG_INF __int_as_float(0xff800000u)
#define IDX_INF 0x7fffffff

// Inter-block scratch (no allocations allowed).
__device__ float g_cand_val[ROWS * KSEL];
__device__ int   g_cand_idx[ROWS * KSEL];
__device__ int   g_batch_done[BSZ];            // zero-init; reset by finisher each replay

__device__ __forceinline__ bool better(float v1, int i1, float v2, int i2) {
    // JAX top_k stability: larger value wins; ties -> smaller index wins.
    return (v1 > v2) || (v1 == v2 && i1 < i2);
}

// Maintain per-thread top-3 (strict > insert keeps earliest/smallest-index on ties;
// invariant: every non-held element of this thread's stream is <= m3).
struct Top3 {
    float m1, m2, m3;
    int   i1, i2, i3;
    __device__ __forceinline__ void init() {
        m1 = m2 = m3 = NEG_INF; i1 = i2 = i3 = IDX_INF;
    }
    __device__ __forceinline__ void push(float v, int ix) {
        if (v > m1)      { m3 = m2; i3 = i2; m2 = m1; i2 = i1; m1 = v; i1 = ix; }
        else if (v > m2) { m3 = m2; i3 = i2; m2 = v;  i2 = ix; }
        else             { m3 = v;  i3 = ix; }          // caller guarantees v > m3
    }
};

__global__ __launch_bounds__(T, 5)
void dss_kernel(const float* __restrict__ lprobs,
                const float* __restrict__ scores,
                const int* __restrict__ step_ptr,
                int score_last_dim,
                float* __restrict__ out) {
    __shared__ float    swtop[2 * NWARP];        // per-warp top-2 of per-thread maxima
    __shared__ float    sthr;
    __shared__ int      sflag;                   // any thread suspicious?
    __shared__ unsigned scount;
    __shared__ float    cval[CAP];
    __shared__ int      cidx[CAP];

    const int row   = blockIdx.x;                // row = batch * BEAM + beam
    const int batch = row / BEAM;
    const int tid   = threadIdx.x;
    const int lane  = tid & 31;
    const int wid   = tid >> 5;
    const float* __restrict__ rp = lprobs + (size_t)row * VOCAB;

    if (tid == 0) { scount = 0u; sflag = 0; }

    // Alignment peel: row*VOCAB mod 4 == row mod 4.
    const int P     = (4 - (row & 3)) & 3;       // head elements (scalar)
    const int nv    = (VOCAB - P) >> 2;          // aligned float4 count
    const int tailn = (VOCAB - P) & 3;           // tail elements (scalar)
    const float4* __restrict__ rp4 = reinterpret_cast<const float4*>(rp + P);

    Top3 t3; t3.init();

    // Head elements -> thread 0's stream (processed first: smallest indices).
    if (tid == 0) {
        for (int i = 0; i < P; ++i) {
            float x = rp[i];
            if (x > t3.m3) t3.push(x, i);
        }
    }

    // ---- Single streaming pass: 8 front-batched LDG.128, quad-max prefilter ----
    int v = tid;
    for (; v + 7 * T < nv; v += 8 * T) {
        float4 q[8];
        q[0] = rp4[v];         q[1] = rp4[v + T];
        q[2] = rp4[v + 2 * T]; q[3] = rp4[v + 3 * T];
        q[4] = rp4[v + 4 * T]; q[5] = rp4[v + 5 * T];
        q[6] = rp4[v + 6 * T]; q[7] = rp4[v + 7 * T];
#pragma unroll
        for (int u = 0; u < 8; ++u) {
            float qm = fmaxf(fmaxf(q[u].x, q[u].y), fmaxf(q[u].z, q[u].w));
            if (qm > t3.m3) {                       // rare
                int i0 = P + 4 * (v + u * T);
                if (q[u].x > t3.m3) t3.push(q[u].x, i0);
                if (q[u].y > t3.m3) t3.push(q[u].y, i0 + 1);
                if (q[u].z > t3.m3) t3.push(q[u].z, i0 + 2);
                if (q[u].w > t3.m3) t3.push(q[u].w, i0 + 3);
            }
        }
    }
    for (; v < nv; v += T) {
        float4 a = rp4[v];
        float qm = fmaxf(fmaxf(a.x, a.y), fmaxf(a.z, a.w));
        if (qm > t3.m3) {
            int i0 = P + 4 * v;
            if (a.x > t3.m3) t3.push(a.x, i0);
            if (a.y > t3.m3) t3.push(a.y, i0 + 1);
            if (a.z > t3.m3) t3.push(a.z, i0 + 2);
            if (a.w > t3.m3) t3.push(a.w, i0 + 3);
        }
    }
    // Tail elements -> thread 1's stream (largest indices, processed last).
    if (tid == 1) {
        for (int q2 = 0; q2 < tailn; ++q2) {
            int i = P + 4 * nv + q2;
            float x = rp[i];
            if (x > t3.m3) t3.push(x, i);
        }
    }

    // ---- Per-warp top-2 of per-thread maxima (2 distinct elements per warp) ----
    {
        float m = t3.m1;
        float w1 = m;
        for (int off = 16; off; off >>= 1) w1 = fmaxf(w1, __shfl_xor_sync(0xffffffffu, w1, off));
        unsigned holders = __ballot_sync(0xffffffffu, m == w1);
        int first = __ffs(holders) - 1;
        float m2 = (lane == first) ? NEG_INF : m;
        float w2 = m2;
        for (int off = 16; off; off >>= 1) w2 = fmaxf(w2, __shfl_xor_sync(0xffffffffu, w2, off));
        if (lane == 0) { swtop[wid] = w1; swtop[NWARP + wid] = w2; }
    }
    __syncthreads();

    // ---- thr = 10th largest of the 2*NWARP = 16 sampled distinct elements.
    // (k-th largest of a subset <= k-th largest of the row: conservative.) ----
    if (tid < 32) {
        float x = (lane < 2 * NWARP) ? swtop[lane] : NEG_INF;
        float t = NEG_INF;
        for (int r = 0; r < KSEL; ++r) {
            float bv = x;
            for (int off = 16; off; off >>= 1) bv = fmaxf(bv, __shfl_xor_sync(0xffffffffu, bv, off));
            unsigned holders = __ballot_sync(0xffffffffu, x == bv);
            int first = __ffs(holders) - 1;
            if (lane == first) x = NEG_INF;      // retire one instance
            t = bv;
        }
        if (lane == 0) sthr = t;
    }
    __syncthreads();
    const float thr = sthr;

    // ---- Suspicion: a dropped element x satisfies x <= m3_final. If m3 >= thr,
    // this thread MIGHT have dropped an element >= thr -> exact block re-scan. ----
    if (t3.m3 >= thr) atomicExch(&sflag, 1);
    __syncthreads();

    if (!sflag) {
        // Emit held values >= thr (contains every row element >= thr; >= 10 of them
        // since the 10 largest sampled values are held and >= thr).
        if (t3.m1 >= thr) { unsigned p = atomicAdd(&scount, 1u); cval[p] = t3.m1; cidx[p] = t3.i1; }
        if (t3.m2 >= thr) { unsigned p = atomicAdd(&scount, 1u); cval[p] = t3.m2; cidx[p] = t3.i2; }
        // m3 < thr here by construction (sflag==0), nothing to emit from m3.
    } else {
        // Rare: exact full re-scan of the row collecting all elements >= thr.
        for (v = tid; v < nv; v += T) {
            float4 a = rp4[v];
            int i0 = P + 4 * v;
            if (a.x >= thr) { unsigned p = atomicAdd(&scount, 1u); if (p < CAP) { cval[p] = a.x; cidx[p] = i0; } }
            if (a.y >= thr) { unsigned p = atomicAdd(&scount, 1u); if (p < CAP) { cval[p] = a.y; cidx[p] = i0 + 1; } }
            if (a.z >= thr) { unsigned p = atomicAdd(&scount, 1u); if (p < CAP) { cval[p] = a.z; cidx[p] = i0 + 2; } }
            if (a.w >= thr) { unsigned p = atomicAdd(&scount, 1u); if (p < CAP) { cval[p] = a.w; cidx[p] = i0 + 3; } }
        }
        if (tid == 0) {
            for (int i = 0; i < P; ++i) {
                float x = rp[i];
                if (x >= thr) { unsigned p = atomicAdd(&scount, 1u); if (p < CAP) { cval[p] = x; cidx[p] = i; } }
            }
        }
        if (tid == 1) {
            for (int q2 = 0; q2 < tailn; ++q2) {
                int i = P + 4 * nv + q2;
                float x = rp[i];
                if (x >= thr) { unsigned p = atomicAdd(&scount, 1u); if (p < CAP) { cval[p] = x; cidx[p] = i; } }
            }
        }
    }
    __syncthreads();

    const unsigned cnt   = scount;
    const int      stepv = step_ptr ? *step_ptr : KSEL;
    const float    base  = scores[row * score_last_dim + (stepv - 1)];

    if (cnt > CAP) {
        // Pathological mass-tie fallback: exact serial top-10.
        if (tid == 0) {
            float val[KSEL]; int idq[KSEL];
#pragma unroll
            for (int q2 = 0; q2 < KSEL; ++q2) { val[q2] = NEG_INF; idq[q2] = IDX_INF; }
            for (int i = 0; i < VOCAB; ++i) {
                float x = rp[i];
                if (better(x, i, val[KSEL - 1], idq[KSEL - 1])) {
                    val[KSEL - 1] = x; idq[KSEL - 1] = i;
#pragma unroll
                    for (int q2 = KSEL - 1; q2 > 0; --q2) {
                        if (better(val[q2], idq[q2], val[q2 - 1], idq[q2 - 1])) {
                            float tv = val[q2]; val[q2] = val[q2 - 1]; val[q2 - 1] = tv;
                            int   ti = idq[q2]; idq[q2] = idq[q2 - 1]; idq[q2 - 1] = ti;
                        }
                    }
                }
            }
#pragma unroll
            for (int r = 0; r < KSEL; ++r) {
                g_cand_val[row * KSEL + r] = (val[r] + base) - (float)(r + 1) * DIV_RATE;
                g_cand_idx[row * KSEL + r] = idq[r];
            }
        }
    } else {
        // Warp-parallel stable top-10 over the candidate set.
        if (tid < 32) {
            for (int r = 0; r < KSEL; ++r) {
                float bv = NEG_INF; int bi = IDX_INF; int bp = -1;
                for (unsigned c = lane; c < cnt; c += 32) {
                    float x = cval[c]; int ix = cidx[c];
                    if (better(x, ix, bv, bi)) { bv = x; bi = ix; bp = (int)c; }
                }
                for (int off = 16; off; off >>= 1) {
                    float ov = __shfl_down_sync(0xffffffffu, bv, off);
                    int   oi = __shfl_down_sync(0xffffffffu, bi, off);
                    int   op = __shfl_down_sync(0xffffffffu, bp, off);
                    if (better(ov, oi, bv, bi)) { bv = ov; bi = oi; bp = op; }
                }
                if (lane == 0) {
                    // ((lprob + base) - penalty): reference op order -> bit-exact.
                    g_cand_val[row * KSEL + r] = (bv + base) - (float)(r + 1) * DIV_RATE;
                    g_cand_idx[row * KSEL + r] = bi;
                    cval[bp] = NEG_INF; cidx[bp] = IDX_INF;
                }
                __syncwarp();
            }
        }
    }

    // ---- Fused finisher: last beam-block of the batch does the 50->10 select ----
    int done = 0;
    if (tid == 0) {
        __threadfence();                              // release g_cand writes
        done = atomicAdd(&g_batch_done[batch], 1);
    }
    if (tid < 32) {
        done = __shfl_sync(0xffffffffu, done, 0);
        if (done == BEAM - 1) {
            __threadfence();                          // acquire peers' g_cand
            const int b50 = batch * BEAM * KSEL;
            float v0 = NEG_INF, v1 = NEG_INF;
            int   p0 = IDX_INF, p1 = IDX_INF;
            if (lane < BEAM * KSEL)      { v0 = __ldcg(&g_cand_val[b50 + lane]);      p0 = lane; }
            if (lane + 32 < BEAM * KSEL) { v1 = __ldcg(&g_cand_val[b50 + lane + 32]); p1 = lane + 32; }
            for (int r = 0; r < KSEL; ++r) {
                float bv; int bp;
                if (better(v0, p0, v1, p1)) { bv = v0; bp = p0; } else { bv = v1; bp = p1; }
                for (int off = 16; off; off >>= 1) {
                    float ov = __shfl_down_sync(0xffffffffu, bv, off);
                    int   op = __shfl_down_sync(0xffffffffu, bp, off);
                    if (better(ov, op, bv, bp)) { bv = ov; bp = op; }
                }
                bv = __shfl_sync(0xffffffffu, bv, 0);
                bp = __shfl_sync(0xffffffffu, bp, 0);
                if (lane == 0) {
                    out[batch * KSEL + r]                  = bv;                                   // scores
                    out[BSZ * KSEL + batch * KSEL + r]     = (float)__ldcg(&g_cand_idx[b50 + bp]); // indices
                    out[2 * BSZ * KSEL + batch * KSEL + r] = (float)(bp / KSEL);                   // beams
                }
                if (p0 == bp) { v0 = NEG_INF; p0 = IDX_INF; }
                if (p1 == bp) { v1 = NEG_INF; p1 = IDX_INF; }
            }
            if (lane == 0) atomicExch(&g_batch_done[batch], 0);   // reset for next replay
        }
    }
}

extern "C" void kernel_launch(void* const* d_in, const int* in_sizes, int n_in,
                              void* d_out, int out_size) {
    const float* lprobs = (const float*)d_in[0];
    const float* scores = (const float*)d_in[1];
    const int*   step   = (n_in >= 3) ? (const int*)d_in[2] : nullptr;
    const int score_last_dim = in_sizes[1] / ROWS;   // = 10

    dss_kernel<<<ROWS, T>>>(lprobs, scores, step, score_last_dim, (float*)d_out);
}

// round 12
// speedup vs baseline: 1.7385x; 1.1741x over previous
#include <cuda_runtime.h>
#include <cstdint>

// DiverseSiblingsSearch on GB300 — single DRAM pass with seg1-sampled conservative
// threshold: no per-thread top-k maintenance in the hot loop.
// lprobs: (128, 5, 50257) f32, scores: (128, 5, 10) f32, step: int scalar (=10).
// Output (f32): final_scores (128,10) | final_indices (128,10) | final_beams (128,10).

#define BSZ     128
#define BEAM    5
#define VOCAB   50257
#define KSEL    10
#define ROWS    (BSZ * BEAM)
#define T       256
#define NWARP   (T / 32)
#define NQ1     12                     // seg1 = first NQ1 strided quads/thread = 12288 elems
#define CAP     1024
#define DIV_RATE 0.5f
#define NEG_INF __int_as_float(0xff800000u)
#define IDX_INF 0x7fffffff

// Inter-block scratch (no allocations allowed).
__device__ float g_cand_val[ROWS * KSEL];
__device__ int   g_cand_idx[ROWS * KSEL];
__device__ int   g_batch_done[BSZ];            // zero-init; reset by finisher each replay

__device__ __forceinline__ bool better(float v1, int i1, float v2, int i2) {
    // JAX top_k stability: larger value wins; ties -> smaller index wins.
    return (v1 > v2) || (v1 == v2 && i1 < i2);
}

__device__ __forceinline__ float4 max4(float4 a, float4 b) {
    return make_float4(fmaxf(a.x, b.x), fmaxf(a.y, b.y), fmaxf(a.z, b.z), fmaxf(a.w, b.w));
}

__global__ __launch_bounds__(T, 5)
void dss_kernel(const float* __restrict__ lprobs,
                const float* __restrict__ scores,
                const int* __restrict__ step_ptr,
                int score_last_dim,
                float* __restrict__ out) {
    __shared__ float    swtop[2 * NWARP];       // per-warp top-2 of seg1 per-thread maxima
    __shared__ float    sthr;
    __shared__ unsigned scount;
    __shared__ float    cval[CAP];
    __shared__ int      cidx[CAP];

    const int row   = blockIdx.x;               // row = batch * BEAM + beam
    const int batch = row / BEAM;
    const int tid   = threadIdx.x;
    const int lane  = tid & 31;
    const int wid   = tid >> 5;
    const float* __restrict__ rp = lprobs + (size_t)row * VOCAB;

    if (tid == 0) scount = 0u;

    // Alignment peel: row*VOCAB mod 4 == row mod 4.
    const int P     = (4 - (row & 3)) & 3;      // head elements (scalar)
    const int nv    = (VOCAB - P) >> 2;         // aligned float4 count (~12564 >= NQ1*T)
    const int tailn = (VOCAB - P) & 3;          // tail elements (scalar)
    const float4* __restrict__ rp4 = reinterpret_cast<const float4*>(rp + P);

    // ---- Phase 1a: branchless max over seg1 (first NQ1 quads/thread) ----
    float4 M0 = make_float4(NEG_INF, NEG_INF, NEG_INF, NEG_INF);
    float4 M1 = M0, M2 = M0, M3 = M0;
#pragma unroll
    for (int j = 0; j < NQ1; j += 4) {
        float4 a = rp4[tid + j * T];
        float4 b = rp4[tid + (j + 1) * T];
        float4 c = rp4[tid + (j + 2) * T];
        float4 d = rp4[tid + (j + 3) * T];
        M0 = max4(M0, a); M1 = max4(M1, b); M2 = max4(M2, c); M3 = max4(M3, d);
    }
    M0 = max4(max4(M0, M1), max4(M2, M3));
    float m = fmaxf(fmaxf(M0.x, M0.y), fmaxf(M0.z, M0.w));

    // ---- Per-warp top-2 of per-thread seg1 maxima (2 distinct elements/warp) ----
    {
        float w1 = m;
        for (int off = 16; off; off >>= 1) w1 = fmaxf(w1, __shfl_xor_sync(0xffffffffu, w1, off));
        unsigned holders = __ballot_sync(0xffffffffu, m == w1);
        int first = __ffs(holders) - 1;
        float m2 = (lane == first) ? NEG_INF : m;
        float w2 = m2;
        for (int off = 16; off; off >>= 1) w2 = fmaxf(w2, __shfl_xor_sync(0xffffffffu, w2, off));
        if (lane == 0) { swtop[wid] = w1; swtop[NWARP + wid] = w2; }
    }
    __syncthreads();

    // ---- thr = 10th largest of 16 distinct seg1 elements.
    // seg1 subset-of row => 10th(seg1 sample) <= 10th(seg1) <= 10th(row):
    // conservative for the WHOLE row, known before 76% of the stream. ----
    if (tid < 32) {
        float x = (lane < 2 * NWARP) ? swtop[lane] : NEG_INF;
        float t = NEG_INF;
        for (int r = 0; r < KSEL; ++r) {
            float bv = x;
            for (int off = 16; off; off >>= 1) bv = fmaxf(bv, __shfl_xor_sync(0xffffffffu, bv, off));
            unsigned holders = __ballot_sync(0xffffffffu, x == bv);
            int first = __ffs(holders) - 1;
            if (lane == first) x = NEG_INF;     // retire one instance
            t = bv;
        }
        if (lane == 0) sthr = t;
    }
    __syncthreads();
    const float thr = sthr;

    // Quad filter: prefilter on quad max, push survivors (exact value+index).
    auto filter_quad = [&](float4 a, int i0) {
        float qm = fmaxf(fmaxf(a.x, a.y), fmaxf(a.z, a.w));
        if (qm >= thr) {                        // rare (~0.5% of quads)
            if (a.x >= thr) { unsigned p = atomicAdd(&scount, 1u); if (p < CAP) { cval[p] = a.x; cidx[p] = i0; } }
            if (a.y >= thr) { unsigned p = atomicAdd(&scount, 1u); if (p < CAP) { cval[p] = a.y; cidx[p] = i0 + 1; } }
            if (a.z >= thr) { unsigned p = atomicAdd(&scount, 1u); if (p < CAP) { cval[p] = a.z; cidx[p] = i0 + 2; } }
            if (a.w >= thr) { unsigned p = atomicAdd(&scount, 1u); if (p < CAP) { cval[p] = a.w; cidx[p] = i0 + 3; } }
        }
    };

    // ---- Phase 1b: re-read seg1 (L1/L2-hot, just streamed) with exact filter ----
#pragma unroll
    for (int j = 0; j < NQ1; j += 4) {
        float4 a = rp4[tid + j * T];
        float4 b = rp4[tid + (j + 1) * T];
        float4 c = rp4[tid + (j + 2) * T];
        float4 d = rp4[tid + (j + 3) * T];
        filter_quad(a, P + 4 * (tid + j * T));
        filter_quad(b, P + 4 * (tid + (j + 1) * T));
        filter_quad(c, P + 4 * (tid + (j + 2) * T));
        filter_quad(d, P + 4 * (tid + (j + 3) * T));
    }

    // ---- Phase 2: rest of the row, single pass, thr known up-front ----
    int v = tid + NQ1 * T;
    for (; v + 3 * T < nv; v += 4 * T) {
        float4 a = rp4[v];
        float4 b = rp4[v + T];
        float4 c = rp4[v + 2 * T];
        float4 d = rp4[v + 3 * T];
        filter_quad(a, P + 4 * v);
        filter_quad(b, P + 4 * (v + T));
        filter_quad(c, P + 4 * (v + 2 * T));
        filter_quad(d, P + 4 * (v + 3 * T));
    }
    for (; v < nv; v += T) filter_quad(rp4[v], P + 4 * v);

    if (tid == 0) {          // head elements, exact test
        for (int i = 0; i < P; ++i) {
            float x = rp[i];
            if (x >= thr) { unsigned p = atomicAdd(&scount, 1u); if (p < CAP) { cval[p] = x; cidx[p] = i; } }
        }
    }
    if (tid == 1) {          // tail elements, exact test
        for (int q = 0; q < tailn; ++q) {
            int i = P + 4 * nv + q;
            float x = rp[i];
            if (x >= thr) { unsigned p = atomicAdd(&scount, 1u); if (p < CAP) { cval[p] = x; cidx[p] = i; } }
        }
    }
    __syncthreads();

    const unsigned cnt   = scount;
    const int      stepv = step_ptr ? *step_ptr : KSEL;
    const float    base  = scores[row * score_last_dim + (stepv - 1)];

    if (cnt > CAP) {
        // Pathological mass-tie fallback: exact serial top-10.
        if (tid == 0) {
            float val[KSEL]; int idq[KSEL];
#pragma unroll
            for (int q = 0; q < KSEL; ++q) { val[q] = NEG_INF; idq[q] = IDX_INF; }
            for (int i = 0; i < VOCAB; ++i) {
                float x = rp[i];
                if (better(x, i, val[KSEL - 1], idq[KSEL - 1])) {
                    val[KSEL - 1] = x; idq[KSEL - 1] = i;
#pragma unroll
                    for (int q = KSEL - 1; q > 0; --q) {
                        if (better(val[q], idq[q], val[q - 1], idq[q - 1])) {
                            float tv = val[q]; val[q] = val[q - 1]; val[q - 1] = tv;
                            int   ti = idq[q]; idq[q] = idq[q - 1]; idq[q - 1] = ti;
                        }
                    }
                }
            }
#pragma unroll
            for (int r = 0; r < KSEL; ++r) {
                g_cand_val[row * KSEL + r] = (val[r] + base) - (float)(r + 1) * DIV_RATE;
                g_cand_idx[row * KSEL + r] = idq[r];
            }
        }
    } else {
        // Warp-parallel stable top-10 over ~50 exact candidates.
        if (tid < 32) {
            for (int r = 0; r < KSEL; ++r) {
                float bv = NEG_INF; int bi = IDX_INF; int bp = -1;
                for (unsigned c = lane; c < cnt; c += 32) {
                    float x = cval[c]; int ix = cidx[c];
                    if (better(x, ix, bv, bi)) { bv = x; bi = ix; bp = (int)c; }
                }
                for (int off = 16; off; off >>= 1) {
                    float ov = __shfl_down_sync(0xffffffffu, bv, off);
                    int   oi = __shfl_down_sync(0xffffffffu, bi, off);
                    int   op = __shfl_down_sync(0xffffffffu, bp, off);
                    if (better(ov, oi, bv, bi)) { bv = ov; bi = oi; bp = op; }
                }
                if (lane == 0) {
                    // ((lprob + base) - penalty): reference op order -> bit-exact.
                    g_cand_val[row * KSEL + r] = (bv + base) - (float)(r + 1) * DIV_RATE;
                    g_cand_idx[row * KSEL + r] = bi;
                    cval[bp] = NEG_INF; cidx[bp] = IDX_INF;
                }
                __syncwarp();
            }
        }
    }

    // ---- Fused finisher: last beam-block of the batch does the 50->10 select ----
    int done = 0;
    if (tid == 0) {
        __threadfence();                              // release g_cand writes
        done = atomicAdd(&g_batch_done[batch], 1);
    }
    if (tid < 32) {
        done = __shfl_sync(0xffffffffu, done, 0);
        if (done == BEAM - 1) {
            __threadfence();                          // acquire peers' g_cand
            const int b50 = batch * BEAM * KSEL;
            float v0 = NEG_INF, v1 = NEG_INF;
            int   p0 = IDX_INF, p1 = IDX_INF;
            if (lane < BEAM * KSEL)      { v0 = __ldcg(&g_cand_val[b50 + lane]);      p0 = lane; }
            if (lane + 32 < BEAM * KSEL) { v1 = __ldcg(&g_cand_val[b50 + lane + 32]); p1 = lane + 32; }
            for (int r = 0; r < KSEL; ++r) {
                float bv; int bp;
                if (better(v0, p0, v1, p1)) { bv = v0; bp = p0; } else { bv = v1; bp = p1; }
                for (int off = 16; off; off >>= 1) {
                    float ov = __shfl_down_sync(0xffffffffu, bv, off);
                    int   op = __shfl_down_sync(0xffffffffu, bp, off);
                    if (better(ov, op, bv, bp)) { bv = ov; bp = op; }
                }
                bv = __shfl_sync(0xffffffffu, bv, 0);
                bp = __shfl_sync(0xffffffffu, bp, 0);
                if (lane == 0) {
                    out[batch * KSEL + r]                  = bv;                                   // scores
                    out[BSZ * KSEL + batch * KSEL + r]     = (float)__ldcg(&g_cand_idx[b50 + bp]); // indices
                    out[2 * BSZ * KSEL + batch * KSEL + r] = (float)(bp / KSEL);                   // beams
                }
                if (p0 == bp) { v0 = NEG_INF; p0 = IDX_INF; }
                if (p1 == bp) { v1 = NEG_INF; p1 = IDX_INF; }
            }
            if (lane == 0) atomicExch(&g_batch_done[batch], 0);   // reset for next replay
        }
    }
}

extern "C" void kernel_launch(void* const* d_in, const int* in_sizes, int n_in,
                              void* d_out, int out_size) {
    const float* lprobs = (const float*)d_in[0];
    const float* scores = (const float*)d_in[1];
    const int*   step   = (n_in >= 3) ? (const int*)d_in[2] : nullptr;
    const int score_last_dim = in_sizes[1] / ROWS;   // = 10

    dss_kernel<<<ROWS, T>>>(lprobs, scores, step, score_last_dim, (float*)d_out);
}